// round 16
// baseline (speedup 1.0000x reference)
#include <cuda_runtime.h>
#include <cuda_bf16.h>
#include <cstdint>

#define D_H 128
#define STRIDE 131
#define MAXN 50000
#define MAXE 800000

// ---- edge smem (bytes) ----
#define W1H_OFF 0u
#define W1L_OFF 75776u
#define X1H_OFF 151552u
#define X1L_OFF 189440u
#define SFI_OFF 227328u
#define SCD_OFF 227840u
#define SCP_OFF 229376u
#define EDGE_SMEM 231424
// ---- node smem (bytes) ----
#define NW1H 0u
#define NW1L 67584u
#define NX1H 135168u
#define NX1L 169984u
#define NODE_SMEM 204800

__device__ float g_nbr[MAXN * D_H];
__device__ float g_csum[MAXN * 3];
__device__ float g_cnt[MAXN];
__device__ uint16_t g_h_hi[MAXN * 128];
__device__ uint16_t g_h_lo[MAXN * 128];
__device__ uint16_t g_nbrh[MAXN * 128];
__device__ uint16_t g_nbrl[MAXN * 128];
__device__ uint16_t g_ef_hi[MAXE * 16];
__device__ uint16_t g_ef_lo[MAXE * 16];
__device__ uint16_t g_W1Th[128 * 288];
__device__ uint16_t g_W1Tl[128 * 288];
__device__ uint16_t g_Wn1Th[128 * 256];
__device__ uint16_t g_Wn1Tl[128 * 256];

__device__ __forceinline__ uint32_t smem_u32(const void* p) {
    uint32_t a;
    asm("{ .reg .u64 t; cvta.to.shared.u64 t, %1; cvt.u32.u64 %0, t; }" : "=r"(a) : "l"(p));
    return a;
}
__device__ __forceinline__ float silu(float x) { return x / (1.0f + __expf(-x)); }
__device__ __forceinline__ void cpa16(uint32_t dst, const void* src) {
    asm volatile("cp.async.ca.shared.global [%0], [%1], 16;" :: "r"(dst), "l"(src));
}
#define CPA_COMMIT() asm volatile("cp.async.commit_group;" ::: "memory")
#define CPA_WAIT0()  asm volatile("cp.async.wait_group 0;" ::: "memory")
__device__ __forceinline__ void sts16(uint32_t a, uint16_t v) { asm volatile("st.shared.u16 [%0], %1;" :: "r"(a), "h"(v)); }
__device__ __forceinline__ void split_bf16(float v, uint16_t& hi, uint16_t& lo) {
    __nv_bfloat16 h = __float2bfloat16(v);
    __nv_bfloat16 l = __float2bfloat16(v - __bfloat162float(h));
    hi = __bfloat16_as_ushort(h); lo = __bfloat16_as_ushort(l);
}
__device__ __forceinline__ void ldsm4(uint32_t a, uint32_t* r) {
    asm volatile("ldmatrix.sync.aligned.m8n8.x4.shared.b16 {%0,%1,%2,%3}, [%4];"
        : "=r"(r[0]), "=r"(r[1]), "=r"(r[2]), "=r"(r[3]) : "r"(a));
}
__device__ __forceinline__ void mma_bf16(float* d, const uint32_t* a, const uint32_t* b) {
    asm volatile("mma.sync.aligned.m16n8k16.row.col.f32.bf16.bf16.f32 "
        "{%0,%1,%2,%3}, {%4,%5,%6,%7}, {%8,%9}, {%0,%1,%2,%3};"
        : "+f"(d[0]), "+f"(d[1]), "+f"(d[2]), "+f"(d[3])
        : "r"(a[0]), "r"(a[1]), "r"(a[2]), "r"(a[3]), "r"(b[0]), "r"(b[1]));
}

// ---------------- prep kernels ----------------
__global__ void prep_all(const float* __restrict__ nf, const float* __restrict__ ef,
                         const float* __restrict__ We1, const float* __restrict__ Wn1,
                         int N, int E) {
    int i = blockIdx.x * blockDim.x + threadIdx.x, s = gridDim.x * blockDim.x;
    float4 z = make_float4(0.f, 0.f, 0.f, 0.f);
    float4* p = (float4*)g_nbr; int n4 = N * D_H / 4;
    for (int k = i; k < n4; k += s) p[k] = z;
    for (int k = i; k < N * 3; k += s) g_csum[k] = 0.f;
    for (int k = i; k < N; k += s) g_cnt[k] = 0.f;
    for (int idx = i; idx < N * 128; idx += s) {
        int n = idx >> 7, j = idx & 127;
        uint16_t h, l; split_bf16(nf[n * STRIDE + 3 + j], h, l);
        g_h_hi[idx] = h; g_h_lo[idx] = l;
    }
    for (int idx = i; idx < E * 16; idx += s) {
        uint16_t h, l; split_bf16(ef[idx], h, l);
        g_ef_hi[idx] = h; g_ef_lo[idx] = l;
    }
    for (int idx = i; idx < 128 * 288; idx += s) {
        int j = idx / 288, k = idx % 288;
        float v = 0.f;
        if (k < 256) v = We1[k * 128 + j];
        else if (k < 272) v = We1[(257 + (k - 256)) * 128 + j];
        else if (k == 272) v = We1[256 * 128 + j];
        uint16_t h, l; split_bf16(v, h, l);
        g_W1Th[idx] = h; g_W1Tl[idx] = l;
    }
    for (int idx = i; idx < 128 * 256; idx += s) {
        int j = idx >> 8, k = idx & 255;
        uint16_t h, l; split_bf16(Wn1[k * 128 + j], h, l);
        g_Wn1Th[idx] = h; g_Wn1Tl[idx] = l;
    }
}
__global__ void split_nbr(int N) {
    int i = blockIdx.x * blockDim.x + threadIdx.x, s = gridDim.x * blockDim.x;
    for (int idx = i; idx < N * 128; idx += s) {
        uint16_t h, l; split_bf16(g_nbr[idx], h, l);
        g_nbrh[idx] = h; g_nbrl[idx] = l;
    }
}

// ---------------- edge kernel ----------------
__device__ __forceinline__ void stage_x1(uint32_t sb, char* smem, int t, int nb,
    const float* __restrict__ nf, const int* __restrict__ first, const int* __restrict__ second, int E)
{
    const int tid = threadIdx.x;
    if (tid < 64) {
        int e = tid, eg = min(t * 64 + e, E - 1);
        int fi = first[eg], si = second[eg];
        ((int*)(smem + SFI_OFF))[nb * 64 + e] = fi;
        float dx = nf[fi * STRIDE] - nf[si * STRIDE];
        float dy = nf[fi * STRIDE + 1] - nf[si * STRIDE + 1];
        float dz = nf[fi * STRIDE + 2] - nf[si * STRIDE + 2];
        float* sc = (float*)(smem + SCD_OFF) + nb * 192;
        sc[e] = dx; sc[64 + e] = dy; sc[128 + e] = dz;
        uint16_t h, l; split_bf16(dx * dx + dy * dy + dz * dz, h, l);
        sts16(sb + X1H_OFF + (uint32_t)((e * 296 + 272) * 2), h);
        sts16(sb + X1L_OFF + (uint32_t)((e * 296 + 272) * 2), l);
    }
    {
        int e = tid & 63, g = (tid >> 6) & 1, mat = tid >> 7;
        int eg = min(t * 64 + e, E - 1);
        const uint16_t* src = (mat ? g_ef_lo : g_ef_hi) + eg * 16 + g * 8;
        cpa16(sb + (mat ? X1L_OFF : X1H_OFF) + (uint32_t)((e * 296 + 256 + g * 8) * 2), src);
    }
    #pragma unroll
    for (int i = 0; i < 16; i++) {
        int idx = tid + i * 256;
        int g = idx & 31, e = (idx >> 5) & 63, mat = idx >> 11;
        int eg = min(t * 64 + e, E - 1);
        int node = (g < 16) ? first[eg] : second[eg];
        const uint16_t* src = (mat ? g_h_lo : g_h_hi) + node * 128 + (g & 15) * 8;
        cpa16(sb + (mat ? X1L_OFF : X1H_OFF) + (uint32_t)((e * 296 + g * 8) * 2), src);
    }
}

__global__ void __launch_bounds__(256, 1) edge_kernel(
    const float* __restrict__ nf, const int* __restrict__ ei,
    const float* __restrict__ be1, const float* __restrict__ We2, const float* __restrict__ be2,
    const float* __restrict__ Wc, const float* __restrict__ bc, int N, int E)
{
    extern __shared__ char smem[];
    const uint32_t sb = smem_u32(smem);
    const int tid = threadIdx.x, w = tid >> 5, lane = tid & 31;
    const int* first = ei;
    const int* second = ei + E;
    int* sfi = (int*)(smem + SFI_OFF);
    float* scp = (float*)(smem + SCP_OFF);

    // layer-2 / epilogue-2 mapping (16j x 64e, as R15)
    const int j1 = 16 * w + (lane >> 2), j2 = j1 + 8;
    const float b2a = be2[j1], b2b = be2[j2];
    const float wc1 = Wc[j1], wc2 = Wc[j2];
    const float bcv = bc[0];
    // layer-1 mapping (4j x 2e warp grid: 32j x 32e per warp)
    const int jg = w >> 1, eh = w & 1;
    const int ja0 = 32 * jg + (lane >> 2);        // mi=0 row a
    const float b1_0a = be1[ja0], b1_0b = be1[ja0 + 8];
    const float b1_1a = be1[ja0 + 16], b1_1b = be1[ja0 + 24];

    const int r_a = (lane & 7) + ((lane >> 3) & 1) * 8;
    const int kk_a = ((lane >> 4) & 1) * 8;
    const uint32_t aoffA0 = (uint32_t)(((32 * jg + r_a) * 296 + kk_a) * 2);
    const uint32_t aoffA1 = (uint32_t)(((32 * jg + 16 + r_a) * 296 + kk_a) * 2);
    const uint32_t aoff136 = (uint32_t)(((16 * w + r_a) * 136 + kk_a) * 2);
    const int e_l = (lane & 7) + (lane >> 4) * 8, khalf = (lane >> 3) & 1;
    const uint32_t boffL1 = (uint32_t)(((32 * eh + e_l) * 296 + khalf * 8) * 2);
    const uint32_t boff4_2 = (uint32_t)((e_l * 136 + khalf * 8) * 2);

    // --- startup: W2 split into X1 scratch, ldsm into registers ---
    for (int idx = tid; idx < 128 * 128; idx += 256) {
        int k = idx >> 7, j = idx & 127;
        uint16_t h, l; split_bf16(We2[k * 128 + j], h, l);
        sts16(sb + X1H_OFF + (uint32_t)((j * 136 + k) * 2), h);
        sts16(sb + X1L_OFF + (uint32_t)((j * 136 + k) * 2), l);
    }
    __syncthreads();
    uint32_t w2h[8][4], w2l[8][4];
    #pragma unroll
    for (int ks = 0; ks < 8; ks++) {
        ldsm4(sb + X1H_OFF + aoff136 + (uint32_t)(ks * 32), w2h[ks]);
        ldsm4(sb + X1L_OFF + aoff136 + (uint32_t)(ks * 32), w2l[ks]);
    }
    __syncthreads();
    for (int idx = tid; idx < 64 * 15; idx += 256) {
        int e = idx / 15, c = 273 + idx % 15;
        sts16(sb + X1H_OFF + (uint32_t)((e * 296 + c) * 2), 0);
        sts16(sb + X1L_OFF + (uint32_t)((e * 296 + c) * 2), 0);
    }
    for (int idx = tid; idx < 128 * 36 * 2; idx += 256) {
        int g = idx % 36, j = (idx / 36) & 127, mat = idx / (36 * 128);
        const uint16_t* src = (mat ? g_W1Tl : g_W1Th) + j * 288 + g * 8;
        cpa16(sb + (mat ? W1L_OFF : W1H_OFF) + (uint32_t)((j * 296 + g * 8) * 2), src);
    }
    const int ntiles = (E + 63) / 64;
    if ((int)blockIdx.x < ntiles)
        stage_x1(sb, smem, blockIdx.x, 0, nf, first, second, E);
    CPA_COMMIT();

    int buf = 0;
    for (int t = blockIdx.x; t < ntiles; t += gridDim.x, buf ^= 1) {
        CPA_WAIT0();
        __syncthreads();

        float acc[2][4][4];   // [mi][ni][frag]
        #pragma unroll
        for (int ni = 0; ni < 4; ni++) {
            acc[0][ni][0] = b1_0a; acc[0][ni][1] = b1_0a; acc[0][ni][2] = b1_0b; acc[0][ni][3] = b1_0b;
            acc[1][ni][0] = b1_1a; acc[1][ni][1] = b1_1a; acc[1][ni][2] = b1_1b; acc[1][ni][3] = b1_1b;
        }

        // ---- layer 1: 18 k-steps, no syncs; 4 A + 4 B ldsm4 per k ----
        #pragma unroll 2
        for (int kc = 0; kc < 18; kc++) {
            uint32_t a0h[4], a0l[4], a1h[4], a1l[4];
            uint32_t kb = (uint32_t)(kc * 32);
            ldsm4(sb + W1H_OFF + aoffA0 + kb, a0h);
            ldsm4(sb + W1L_OFF + aoffA0 + kb, a0l);
            ldsm4(sb + W1H_OFF + aoffA1 + kb, a1h);
            ldsm4(sb + W1L_OFF + aoffA1 + kb, a1l);
            #pragma unroll
            for (int p = 0; p < 2; p++) {
                uint32_t bh[4], bl[4];
                uint32_t bB = sb + boffL1 + (uint32_t)(p * 9472) + kb;
                ldsm4(bB + X1H_OFF, bh);
                ldsm4(bB + X1L_OFF, bl);
                mma_bf16(acc[0][2 * p], a0h, bh);     mma_bf16(acc[0][2 * p], a0h, bl);     mma_bf16(acc[0][2 * p], a0l, bh);
                mma_bf16(acc[0][2 * p + 1], a0h, bh + 2); mma_bf16(acc[0][2 * p + 1], a0h, bl + 2); mma_bf16(acc[0][2 * p + 1], a0l, bh + 2);
                mma_bf16(acc[1][2 * p], a1h, bh);     mma_bf16(acc[1][2 * p], a1h, bl);     mma_bf16(acc[1][2 * p], a1l, bh);
                mma_bf16(acc[1][2 * p + 1], a1h, bh + 2); mma_bf16(acc[1][2 * p + 1], a1h, bl + 2); mma_bf16(acc[1][2 * p + 1], a1l, bh + 2);
            }
        }
        __syncthreads();   // all warps done reading X1 before X2 overlay

        // ---- epi1: silu -> X2 (overlay, stride 136), scatter from new layout ----
        #pragma unroll
        for (int mi = 0; mi < 2; mi++) {
            int j_a = ja0 + 16 * mi, j_b = j_a + 8;
            #pragma unroll
            for (int ni = 0; ni < 4; ni++) {
                int e0 = 32 * eh + 8 * ni + 2 * (lane & 3);
                float v[4] = { silu(acc[mi][ni][0]), silu(acc[mi][ni][1]), silu(acc[mi][ni][2]), silu(acc[mi][ni][3]) };
                const int ee[4] = { e0, e0 + 1, e0, e0 + 1 };
                const int jj[4] = { j_a, j_a, j_b, j_b };
                #pragma unroll
                for (int q = 0; q < 4; q++) {
                    uint16_t h, l; split_bf16(v[q], h, l);
                    uint32_t o = (uint32_t)((ee[q] * 136 + jj[q]) * 2);
                    sts16(sb + X1H_OFF + o, h);
                    sts16(sb + X1L_OFF + o, l);
                }
            }
        }
        __syncthreads();

        // ---- layer 2: W2 from registers (16j x 64e mapping) ----
        float a2[8][4];
        #pragma unroll
        for (int n = 0; n < 8; n++) { a2[n][0] = b2a; a2[n][1] = b2a; a2[n][2] = b2b; a2[n][3] = b2b; }
        #pragma unroll
        for (int ks = 0; ks < 8; ks++) {
            uint32_t bB = sb + X1H_OFF + boff4_2 + (uint32_t)(ks * 32);
            #pragma unroll
            for (int p = 0; p < 4; p++) {
                uint32_t bh[4], bl[4];
                ldsm4(bB + (uint32_t)(p * 4352), bh);
                ldsm4(bB + (X1L_OFF - X1H_OFF) + (uint32_t)(p * 4352), bl);
                mma_bf16(a2[2 * p], w2h[ks], bh);     mma_bf16(a2[2 * p], w2h[ks], bl);     mma_bf16(a2[2 * p], w2l[ks], bh);
                mma_bf16(a2[2 * p + 1], w2h[ks], bh + 2); mma_bf16(a2[2 * p + 1], w2h[ks], bl + 2); mma_bf16(a2[2 * p + 1], w2l[ks], bh + 2);
            }
        }
        __syncthreads();   // X2 consumed; safe to restage X1

        int tn = t + gridDim.x;
        if (tn < ntiles)
            stage_x1(sb, smem, tn, buf ^ 1, nf, first, second, E);
        CPA_COMMIT();

        // ---- epi2: silu -> atomics + coord gate ----
        #pragma unroll
        for (int n = 0; n < 8; n++) {
            int e0 = 8 * n + 2 * (lane & 3);
            float m0 = silu(a2[n][0]), m1 = silu(a2[n][1]), m2 = silu(a2[n][2]), m3 = silu(a2[n][3]);
            int ge0 = t * 64 + e0;
            if (ge0 < E) {
                int f0 = sfi[buf * 64 + e0];
                atomicAdd(&g_nbr[f0 * 128 + j1], m0);
                atomicAdd(&g_nbr[f0 * 128 + j2], m2);
            }
            if (ge0 + 1 < E) {
                int f1 = sfi[buf * 64 + e0 + 1];
                atomicAdd(&g_nbr[f1 * 128 + j1], m1);
                atomicAdd(&g_nbr[f1 * 128 + j2], m3);
            }
            float p0 = m0 * wc1 + m2 * wc2, p1 = m1 * wc1 + m3 * wc2;
            p0 += __shfl_xor_sync(~0u, p0, 4);  p1 += __shfl_xor_sync(~0u, p1, 4);
            p0 += __shfl_xor_sync(~0u, p0, 8);  p1 += __shfl_xor_sync(~0u, p1, 8);
            p0 += __shfl_xor_sync(~0u, p0, 16); p1 += __shfl_xor_sync(~0u, p1, 16);
            if ((lane >> 2) == 0) { scp[w * 64 + e0] = p0; scp[w * 64 + e0 + 1] = p1; }
        }
        __syncthreads();
        if (tid < 64 && t * 64 + tid < E) {
            int e = tid, fi = sfi[buf * 64 + e];
            float c = bcv;
            #pragma unroll
            for (int k2 = 0; k2 < 8; k2++) c += scp[k2 * 64 + e];
            float* sc = (float*)(smem + SCD_OFF) + buf * 192;
            atomicAdd(&g_csum[fi * 3 + 0], sc[e] * c);
            atomicAdd(&g_csum[fi * 3 + 1], sc[64 + e] * c);
            atomicAdd(&g_csum[fi * 3 + 2], sc[128 + e] * c);
            atomicAdd(&g_cnt[fi], 1.0f);
        }
    }
}

// ---------------- node kernel ----------------
__device__ __forceinline__ void nstage_x1(uint32_t sb, int t, int N) {
    const int tid = threadIdx.x;
    #pragma unroll
    for (int i = 0; i < 16; i++) {
        int idx = tid + i * 256;
        int g = idx & 31, n = (idx >> 5) & 63, mat = idx >> 11;
        int ng = min(t * 64 + n, N - 1);
        const uint16_t* src = (g < 16)
            ? ((mat ? g_h_lo : g_h_hi) + ng * 128 + g * 8)
            : ((mat ? g_nbrl : g_nbrh) + ng * 128 + (g - 16) * 8);
        cpa16(sb + (mat ? NX1L : NX1H) + (uint32_t)((n * 264 + g * 8) * 2), src);
    }
}

__global__ void __launch_bounds__(256, 1) node_kernel(
    const float* __restrict__ nf,
    const float* __restrict__ bn1, const float* __restrict__ Wn2, const float* __restrict__ bn2,
    float* __restrict__ out, int N)
{
    extern __shared__ char smem[];
    const uint32_t sb = smem_u32(smem);
    const int tid = threadIdx.x, w = tid >> 5, lane = tid & 31;

    const int j1 = 16 * w + (lane >> 2), j2 = j1 + 8;
    const float b2a = bn2[j1], b2b = bn2[j2];
    const int jg = w >> 1, eh = w & 1;
    const int ja0 = 32 * jg + (lane >> 2);
    const float b1_0a = bn1[ja0], b1_0b = bn1[ja0 + 8];
    const float b1_1a = bn1[ja0 + 16], b1_1b = bn1[ja0 + 24];

    const int r_a = (lane & 7) + ((lane >> 3) & 1) * 8;
    const int kk_a = ((lane >> 4) & 1) * 8;
    const uint32_t aoffA0 = (uint32_t)(((32 * jg + r_a) * 264 + kk_a) * 2);
    const uint32_t aoffA1 = (uint32_t)(((32 * jg + 16 + r_a) * 264 + kk_a) * 2);
    const uint32_t aoff136 = (uint32_t)(((16 * w + r_a) * 136 + kk_a) * 2);
    const int e_l = (lane & 7) + (lane >> 4) * 8, khalf = (lane >> 3) & 1;
    const uint32_t boffL1 = (uint32_t)(((32 * eh + e_l) * 264 + khalf * 8) * 2);
    const uint32_t boff4_2 = (uint32_t)((e_l * 136 + khalf * 8) * 2);

    for (int idx = tid; idx < 128 * 128; idx += 256) {
        int k = idx >> 7, j = idx & 127;
        uint16_t h, l; split_bf16(Wn2[k * 128 + j], h, l);
        sts16(sb + NX1H + (uint32_t)((j * 136 + k) * 2), h);
        sts16(sb + NX1L + (uint32_t)((j * 136 + k) * 2), l);
    }
    __syncthreads();
    uint32_t w2h[8][4], w2l[8][4];
    #pragma unroll
    for (int ks = 0; ks < 8; ks++) {
        ldsm4(sb + NX1H + aoff136 + (uint32_t)(ks * 32), w2h[ks]);
        ldsm4(sb + NX1L + aoff136 + (uint32_t)(ks * 32), w2l[ks]);
    }
    __syncthreads();
    for (int idx = tid; idx < 128 * 32 * 2; idx += 256) {
        int g = idx & 31, j = (idx >> 5) & 127, mat = idx >> 12;
        const uint16_t* src = (mat ? g_Wn1Tl : g_Wn1Th) + j * 256 + g * 8;
        cpa16(sb + (mat ? NW1L : NW1H) + (uint32_t)((j * 264 + g * 8) * 2), src);
    }
    const int ntiles = (N + 63) / 64;
    if ((int)blockIdx.x < ntiles) nstage_x1(sb, blockIdx.x, N);
    CPA_COMMIT();

    for (int t = blockIdx.x; t < ntiles; t += gridDim.x) {
        CPA_WAIT0();
        __syncthreads();

        float acc[2][4][4];
        #pragma unroll
        for (int ni = 0; ni < 4; ni++) {
            acc[0][ni][0] = b1_0a; acc[0][ni][1] = b1_0a; acc[0][ni][2] = b1_0b; acc[0][ni][3] = b1_0b;
            acc[1][ni][0] = b1_1a; acc[1][ni][1] = b1_1a; acc[1][ni][2] = b1_1b; acc[1][ni][3] = b1_1b;
        }

        #pragma unroll 2
        for (int kc = 0; kc < 16; kc++) {
            uint32_t a0h[4], a0l[4], a1h[4], a1l[4];
            uint32_t kb = (uint32_t)(kc * 32);
            ldsm4(sb + NW1H + aoffA0 + kb, a0h);
            ldsm4(sb + NW1L + aoffA0 + kb, a0l);
            ldsm4(sb + NW1H + aoffA1 + kb, a1h);
            ldsm4(sb + NW1L + aoffA1 + kb, a1l);
            #pragma unroll
            for (int p = 0; p < 2; p++) {
                uint32_t bh[4], bl[4];
                uint32_t bB = sb + boffL1 + (uint32_t)(p * 8448) + kb;
                ldsm4(bB + NX1H, bh);
                ldsm4(bB + NX1L, bl);
                mma_bf16(acc[0][2 * p], a0h, bh);     mma_bf16(acc[0][2 * p], a0h, bl);     mma_bf16(acc[0][2 * p], a0l, bh);
                mma_bf16(acc[0][2 * p + 1], a0h, bh + 2); mma_bf16(acc[0][2 * p + 1], a0h, bl + 2); mma_bf16(acc[0][2 * p + 1], a0l, bh + 2);
                mma_bf16(acc[1][2 * p], a1h, bh);     mma_bf16(acc[1][2 * p], a1h, bl);     mma_bf16(acc[1][2 * p], a1l, bh);
                mma_bf16(acc[1][2 * p + 1], a1h, bh + 2); mma_bf16(acc[1][2 * p + 1], a1h, bl + 2); mma_bf16(acc[1][2 * p + 1], a1l, bh + 2);
            }
        }
        __syncthreads();

        #pragma unroll
        for (int mi = 0; mi < 2; mi++) {
            int j_a = ja0 + 16 * mi, j_b = j_a + 8;
            #pragma unroll
            for (int ni = 0; ni < 4; ni++) {
                int e0 = 32 * eh + 8 * ni + 2 * (lane & 3);
                float v[4] = { silu(acc[mi][ni][0]), silu(acc[mi][ni][1]), silu(acc[mi][ni][2]), silu(acc[mi][ni][3]) };
                const int ee[4] = { e0, e0 + 1, e0, e0 + 1 };
                const int jj[4] = { j_a, j_a, j_b, j_b };
                #pragma unroll
                for (int q = 0; q < 4; q++) {
                    uint16_t h, l; split_bf16(v[q], h, l);
                    uint32_t o = (uint32_t)((ee[q] * 136 + jj[q]) * 2);
                    sts16(sb + NX1H + o, h);
                    sts16(sb + NX1L + o, l);
                }
            }
        }
        __syncthreads();

        float a2[8][4];
        #pragma unroll
        for (int n = 0; n < 8; n++) { a2[n][0] = b2a; a2[n][1] = b2a; a2[n][2] = b2b; a2[n][3] = b2b; }
        #pragma unroll
        for (int ks = 0; ks < 8; ks++) {
            uint32_t bB = sb + NX1H + boff4_2 + (uint32_t)(ks * 32);
            #pragma unroll
            for (int p = 0; p < 4; p++) {
                uint32_t bh[4], bl[4];
                ldsm4(bB + (uint32_t)(p * 4352), bh);
                ldsm4(bB + (NX1L - NX1H) + (uint32_t)(p * 4352), bl);
                mma_bf16(a2[2 * p], w2h[ks], bh);     mma_bf16(a2[2 * p], w2h[ks], bl);     mma_bf16(a2[2 * p], w2l[ks], bh);
                mma_bf16(a2[2 * p + 1], w2h[ks], bh + 2); mma_bf16(a2[2 * p + 1], w2h[ks], bl + 2); mma_bf16(a2[2 * p + 1], w2l[ks], bh + 2);
            }
        }
        __syncthreads();

        int tn = t + gridDim.x;
        if (tn < ntiles) nstage_x1(sb, tn, N);
        CPA_COMMIT();

        #pragma unroll
        for (int n = 0; n < 8; n++) {
            int e0 = 8 * n + 2 * (lane & 3);
            int n0g = t * 64 + e0;
            if (n0g < N) {
                out[n0g * STRIDE + 3 + j1] = a2[n][0];
                out[n0g * STRIDE + 3 + j2] = a2[n][2];
            }
            if (n0g + 1 < N) {
                out[(n0g + 1) * STRIDE + 3 + j1] = a2[n][1];
                out[(n0g + 1) * STRIDE + 3 + j2] = a2[n][3];
            }
        }
        if (tid < 64) {
            int n = t * 64 + tid;
            if (n < N) {
                float inv = 1.0f / fmaxf(g_cnt[n], 1.0f);
                out[n * STRIDE + 0] = nf[n * STRIDE + 0] + g_csum[n * 3 + 0] * inv;
                out[n * STRIDE + 1] = nf[n * STRIDE + 1] + g_csum[n * 3 + 1] * inv;
                out[n * STRIDE + 2] = nf[n * STRIDE + 2] + g_csum[n * 3 + 2] * inv;
            }
        }
    }
}

extern "C" void kernel_launch(void* const* d_in, const int* in_sizes, int n_in,
                              void* d_out, int out_size) {
    const float* nf  = (const float*)d_in[0];
    const int*   ei  = (const int*)d_in[1];
    const float* ef  = (const float*)d_in[2];
    const float* We1 = (const float*)d_in[3];
    const float* be1 = (const float*)d_in[4];
    const float* We2 = (const float*)d_in[5];
    const float* be2 = (const float*)d_in[6];
    const float* Wc  = (const float*)d_in[7];
    const float* bc  = (const float*)d_in[8];
    const float* Wn1 = (const float*)d_in[9];
    const float* bn1 = (const float*)d_in[10];
    const float* Wn2 = (const float*)d_in[11];
    const float* bn2 = (const float*)d_in[12];
    float* out = (float*)d_out;
    const int N = in_sizes[0] / STRIDE;
    const int E = in_sizes[2] / 16;

    cudaFuncSetAttribute(edge_kernel, cudaFuncAttributeMaxDynamicSharedMemorySize, EDGE_SMEM);
    cudaFuncSetAttribute(node_kernel, cudaFuncAttributeMaxDynamicSharedMemorySize, NODE_SMEM);

    prep_all<<<1024, 256>>>(nf, ef, We1, Wn1, N, E);
    edge_kernel<<<148, 256, EDGE_SMEM>>>(nf, ei, be1, We2, be2, Wc, bc, N, E);
    split_nbr<<<512, 256>>>(N);
    node_kernel<<<148, 256, NODE_SMEM>>>(nf, bn1, Wn2, bn2, out, N);
}